// round 1
// baseline (speedup 1.0000x reference)
#include <cuda_runtime.h>
#include <cstdint>

#define T 8
#define V 10000
#define E 100000
#define C_IN 128
#define H 256
#define DS 16
#define C_OUT 64
#define HD (H * DS)  // 4096

// ---------------------------------------------------------------------------
// Scratch (device globals; no allocation allowed)
// ---------------------------------------------------------------------------
__device__ __align__(128) float g_x0[(size_t)T * V * C_IN];   // token-mixed input
__device__ __align__(128) float g_x1[(size_t)T * V * H];      // layer-0 output
__device__ __align__(128) float g_h [(size_t)T * V * H];      // sage output
__device__ __align__(128) float g_xsr[(size_t)T * V * H];     // residual
__device__ __align__(128) float g_agg[(size_t)T * V * H];     // scatter accum / mean
__device__ __align__(128) float g_deg[(size_t)T * V];
__device__ __align__(128) float g_state[(size_t)V * HD];      // SSM state
__device__ __align__(128) float g_lam[2 * HD];
__device__ __align__(128) float g_xlast[(size_t)V * H];
__device__ __align__(128) float g_xsrl [(size_t)V * H];
__device__ int g_is64;

// ---------------------------------------------------------------------------
// Small kernels
// ---------------------------------------------------------------------------
__global__ void zero_kernel(float4* p, long long n4) {
    long long i = blockIdx.x * (long long)blockDim.x + threadIdx.x;
    long long stride = (long long)gridDim.x * blockDim.x;
    for (; i < n4; i += stride) p[i] = make_float4(0.f, 0.f, 0.f, 0.f);
}

// Detect edge_index element width: if int64 with values < 2^31, every high
// 32-bit word is zero.  P(false positive with int32 data) ~ (1e-4)^64.
__global__ void detect_kernel(const unsigned int* ei) {
    if (threadIdx.x == 0 && blockIdx.x == 0) {
        unsigned int s = 0;
        for (int i = 0; i < 64; i++) s |= ei[2 * i + 1];
        g_is64 = (s == 0) ? 1 : 0;
    }
}

__device__ __forceinline__ int load_edge(const void* ei, long long pos) {
    if (g_is64) return (int)((const long long*)ei)[pos];
    return ((const int*)ei)[pos];
}

__global__ void lam_kernel(const float* a0, const float* a1, float* lam) {
    int i = blockIdx.x * blockDim.x + threadIdx.x;
    if (i < HD)           lam[i] = expf(-expf(a0[i]));
    else if (i < 2 * HD)  lam[i] = expf(-expf(a1[i - HD]));
}

// depthwise conv1d over time, kernel 3, zero pad 1
__global__ void token_mix_kernel(const float* __restrict__ xs,
                                 const float* __restrict__ w,
                                 const float* __restrict__ b,
                                 float* __restrict__ out) {
    int idx = blockIdx.x * blockDim.x + threadIdx.x;
    if (idx >= T * V * C_IN) return;
    int c = idx % C_IN;
    int t = idx / (V * C_IN);
    float acc = b[c] + xs[idx] * w[c * 3 + 1];
    if (t > 0)     acc += xs[idx - V * C_IN] * w[c * 3 + 0];
    if (t < T - 1) acc += xs[idx + V * C_IN] * w[c * 3 + 2];
    out[idx] = acc;
}

__global__ void deg_kernel(const void* __restrict__ ei, float* __restrict__ deg) {
    long long i = blockIdx.x * (long long)blockDim.x + threadIdx.x;
    if (i >= (long long)T * E) return;
    int e = (int)(i % E);
    int t = (int)(i / E);
    int dst = load_edge(ei, (long long)t * 2 * E + E + e);
    atomicAdd(&deg[(long long)t * V + dst], 1.0f);
}

// agg[t, dst, :] += x[t, src, :]  (vector atomics, 4 floats/op)
__global__ void scatter_kernel(const float* __restrict__ x, const void* __restrict__ ei,
                               float* __restrict__ agg, int C) {
    int chunks = C >> 2;
    long long idx = blockIdx.x * (long long)blockDim.x + threadIdx.x;
    long long total = (long long)T * E * chunks;
    if (idx >= total) return;
    int c4 = (int)(idx % chunks);
    long long te = idx / chunks;
    int e = (int)(te % E);
    int t = (int)(te / E);
    long long base = (long long)t * 2 * E;
    int src = load_edge(ei, base + e);
    int dst = load_edge(ei, base + E + e);
    float4 v = *(const float4*)&x[((long long)t * V + src) * C + c4 * 4];
    float* p = &agg[((long long)t * V + dst) * C + c4 * 4];
    asm volatile("red.global.add.v4.f32 [%0], {%1,%2,%3,%4};"
                 :: "l"(p), "f"(v.x), "f"(v.y), "f"(v.z), "f"(v.w) : "memory");
}

__global__ void mean_kernel(float* __restrict__ agg, const float* __restrict__ deg, int C) {
    int chunks = C >> 2;
    long long idx = blockIdx.x * (long long)blockDim.x + threadIdx.x;
    long long total = (long long)T * V * chunks;
    if (idx >= total) return;
    long long row = idx / chunks;
    int c4 = (int)(idx % chunks);
    float inv = 1.0f / fmaxf(deg[row], 1.0f);
    float4* p = (float4*)&agg[row * C + c4 * 4];
    float4 v = *p;
    v.x *= inv; v.y *= inv; v.z *= inv; v.w *= inv;
    *p = v;
}

// state = lam * state + h_t[:, :, None] * B   (state kept pre-relu)
__global__ void ssm_update_kernel(const float* __restrict__ h_t,
                                  float* __restrict__ state,
                                  const float* __restrict__ lam,
                                  const float* __restrict__ Bp) {
    long long idx = blockIdx.x * (long long)blockDim.x + threadIdx.x;
    if (idx >= (long long)V * HD / 4) return;
    long long base = idx * 4;
    int hd = (int)(base % HD);
    int v  = (int)(base / HD);
    int hh = hd / DS;
    float4 s = *(float4*)&state[base];
    float4 l = *(const float4*)&lam[hd];
    float4 b = *(const float4*)&Bp[hd];
    float x = h_t[(long long)v * H + hh];
    s.x = l.x * s.x + x * b.x;
    s.y = l.y * s.y + x * b.y;
    s.z = l.z * s.z + x * b.z;
    s.w = l.w * s.w + x * b.w;
    *(float4*)&state[base] = s;
}

// ---------------------------------------------------------------------------
// Tiled SGEMM: C[M,N] = op(A)[M,K] @ B[K,N] + bias[N] + D[M,N]
// op = relu if RELU_A.  128x128 tile, BK=8, 256 threads, 8x8 per thread.
// Requires K % 8 == 0, N % 4 == 0.
// ---------------------------------------------------------------------------
#define BM 128
#define BN 128
#define BK 8

template <bool RELU_A>
__global__ __launch_bounds__(256) void sgemm_kernel(
    const float* __restrict__ A, const float* __restrict__ B,
    const float* __restrict__ bias, const float* __restrict__ D,
    float* __restrict__ C, int M, int N, int K)
{
    __shared__ float As[BK][BM];
    __shared__ float Bs[BK][BN];

    int row0 = blockIdx.y * BM;
    int col0 = blockIdx.x * BN;
    int tid = threadIdx.x;

    int aRow = tid >> 1;            // 0..127
    int aCol = (tid & 1) * 4;       // 0 or 4
    int bRow = tid >> 5;            // 0..7
    int bCol = (tid & 31) * 4;      // 0..124

    int tx = tid & 15;
    int ty = tid >> 4;

    float acc[8][8];
#pragma unroll
    for (int i = 0; i < 8; i++)
#pragma unroll
        for (int j = 0; j < 8; j++) acc[i][j] = 0.f;

    int nK = K / BK;
    for (int kt = 0; kt < nK; ++kt) {
        int k0 = kt * BK;
        float4 av = make_float4(0.f, 0.f, 0.f, 0.f);
        int gr = row0 + aRow;
        if (gr < M) av = *(const float4*)&A[(long long)gr * K + k0 + aCol];
        if (RELU_A) {
            av.x = fmaxf(av.x, 0.f); av.y = fmaxf(av.y, 0.f);
            av.z = fmaxf(av.z, 0.f); av.w = fmaxf(av.w, 0.f);
        }
        As[aCol + 0][aRow] = av.x;
        As[aCol + 1][aRow] = av.y;
        As[aCol + 2][aRow] = av.z;
        As[aCol + 3][aRow] = av.w;

        float4 bv = make_float4(0.f, 0.f, 0.f, 0.f);
        int gc = col0 + bCol;
        if (gc < N) bv = *(const float4*)&B[(long long)(k0 + bRow) * N + gc];
        *(float4*)&Bs[bRow][bCol] = bv;

        __syncthreads();
#pragma unroll
        for (int k = 0; k < BK; k++) {
            float ar[8], br[8];
#pragma unroll
            for (int i = 0; i < 8; i++) ar[i] = As[k][ty * 8 + i];
#pragma unroll
            for (int j = 0; j < 8; j++) br[j] = Bs[k][tx * 8 + j];
#pragma unroll
            for (int i = 0; i < 8; i++)
#pragma unroll
                for (int j = 0; j < 8; j++) acc[i][j] += ar[i] * br[j];
        }
        __syncthreads();
    }

#pragma unroll
    for (int i = 0; i < 8; i++) {
        int r = row0 + ty * 8 + i;
        if (r >= M) continue;
#pragma unroll
        for (int j = 0; j < 8; j++) {
            int c = col0 + tx * 8 + j;
            if (c >= N) continue;
            float v = acc[i][j];
            if (bias) v += bias[c];
            if (D)    v += D[(long long)r * N + c];
            C[(long long)r * N + c] = v;
        }
    }
}

static void sgemm(const float* A, const float* B, const float* bias, const float* D,
                  float* C, int M, int N, int K, bool reluA) {
    dim3 grid((N + BN - 1) / BN, (M + BM - 1) / BM);
    if (reluA) sgemm_kernel<true ><<<grid, 256>>>(A, B, bias, D, C, M, N, K);
    else       sgemm_kernel<false><<<grid, 256>>>(A, B, bias, D, C, M, N, K);
}

static void zero_buf(float* p, long long n_floats) {
    zero_kernel<<<1024, 256>>>((float4*)p, n_floats / 4);
}

// ---------------------------------------------------------------------------
// Launch
// ---------------------------------------------------------------------------
extern "C" void kernel_launch(void* const* d_in, const int* in_sizes, int n_in,
                              void* d_out, int out_size) {
    const float* xs      = (const float*)d_in[0];
    const void*  ei      = d_in[1];
    const float* w_pre   = (const float*)d_in[2];
    const float* b_pre   = (const float*)d_in[3];

    const float* w_res0  = (const float*)d_in[4];
    const float* b_res0  = (const float*)d_in[5];
    const float* w_self0 = (const float*)d_in[6];
    const float* w_neigh0= (const float*)d_in[7];
    const float* b_sage0 = (const float*)d_in[8];
    const float* a_log0  = (const float*)d_in[9];
    const float* B0      = (const float*)d_in[10];
    const float* w_mix0  = (const float*)d_in[11];
    const float* b_mix0  = (const float*)d_in[12];

    const float* w_res1  = (const float*)d_in[13];
    const float* b_res1  = (const float*)d_in[14];
    const float* w_self1 = (const float*)d_in[15];
    const float* w_neigh1= (const float*)d_in[16];
    const float* b_sage1 = (const float*)d_in[17];
    const float* a_log1  = (const float*)d_in[18];
    const float* B1      = (const float*)d_in[19];
    const float* w_mix1  = (const float*)d_in[20];
    const float* b_mix1  = (const float*)d_in[21];

    const float* w_out   = (const float*)d_in[22];
    const float* b_out   = (const float*)d_in[23];

    float *x0, *x1, *h, *xsr, *agg, *deg, *state, *lam, *xlast, *xsrl;
    cudaGetSymbolAddress((void**)&x0,    g_x0);
    cudaGetSymbolAddress((void**)&x1,    g_x1);
    cudaGetSymbolAddress((void**)&h,     g_h);
    cudaGetSymbolAddress((void**)&xsr,   g_xsr);
    cudaGetSymbolAddress((void**)&agg,   g_agg);
    cudaGetSymbolAddress((void**)&deg,   g_deg);
    cudaGetSymbolAddress((void**)&state, g_state);
    cudaGetSymbolAddress((void**)&lam,   g_lam);
    cudaGetSymbolAddress((void**)&xlast, g_xlast);
    cudaGetSymbolAddress((void**)&xsrl,  g_xsrl);

    detect_kernel<<<1, 32>>>((const unsigned int*)ei);
    lam_kernel<<<(2 * HD + 255) / 256, 256>>>(a_log0, a_log1, lam);
    token_mix_kernel<<<(T * V * C_IN + 255) / 256, 256>>>(xs, w_pre, b_pre, x0);

    const long long TVH = (long long)T * V * H;

    // ---------------- layer 0 (input x0, C=C_IN) ----------------
    zero_buf(agg, (long long)T * V * C_IN);
    zero_buf(deg, (long long)T * V);
    deg_kernel<<<(int)(((long long)T * E + 255) / 256), 256>>>(ei, deg);
    {
        long long tot = (long long)T * E * (C_IN / 4);
        scatter_kernel<<<(int)((tot + 255) / 256), 256>>>(x0, ei, agg, C_IN);
        long long tm = (long long)T * V * (C_IN / 4);
        mean_kernel<<<(int)((tm + 255) / 256), 256>>>(agg, deg, C_IN);
    }
    sgemm(x0,  w_self0,  b_sage0, nullptr, h,   T * V, H, C_IN, false);
    sgemm(agg, w_neigh0, nullptr, h,       h,   T * V, H, C_IN, false);
    sgemm(x0,  w_res0,   b_res0,  nullptr, xsr, T * V, H, C_IN, false);

    zero_buf(state, (long long)V * HD);
    for (int t = 0; t < T; t++) {
        const float* h_t = h + (long long)t * V * H;
        ssm_update_kernel<<<(int)(((long long)V * HD / 4 + 255) / 256), 256>>>(
            h_t, state, lam, B0);
        sgemm(state, w_mix0, b_mix0, xsr + (long long)t * V * H,
              x1 + (long long)t * V * H, V, H, HD, true);
    }

    // ---------------- layer 1 (input x1, C=H) ----------------
    zero_buf(agg, TVH);
    zero_buf(deg, (long long)T * V);
    deg_kernel<<<(int)(((long long)T * E + 255) / 256), 256>>>(ei, deg);
    {
        long long tot = (long long)T * E * (H / 4);
        scatter_kernel<<<(int)((tot + 255) / 256), 256>>>(x1, ei, agg, H);
        long long tm = (long long)T * V * (H / 4);
        mean_kernel<<<(int)((tm + 255) / 256), 256>>>(agg, deg, H);
    }
    sgemm(x1,  w_self1,  b_sage1, nullptr, h, T * V, H, H, false);
    sgemm(agg, w_neigh1, nullptr, h,       h, T * V, H, H, false);
    // residual only needed at t = T-1 (only xs1[-1] feeds the output head)
    sgemm(x1 + (long long)(T - 1) * V * H, w_res1, b_res1, nullptr, xsrl, V, H, H, false);

    zero_buf(state, (long long)V * HD);
    for (int t = 0; t < T; t++) {
        const float* h_t = h + (long long)t * V * H;
        ssm_update_kernel<<<(int)(((long long)V * HD / 4 + 255) / 256), 256>>>(
            h_t, state, lam + HD, B1);
        if (t == T - 1) {
            // mix GEMM only needed at the final timestep
            sgemm(state, w_mix1, b_mix1, xsrl, xlast, V, H, HD, true);
        }
    }

    // ---------------- output head ----------------
    sgemm(xlast, w_out, b_out, nullptr, (float*)d_out, V, C_OUT, H, false);
}

// round 3
// speedup vs baseline: 2.3646x; 2.3646x over previous
#include <cuda_runtime.h>
#include <cuda_bf16.h>
#include <cstdint>

#define T 8
#define V 10000
#define E 100000
#define C_IN 128
#define H 256
#define DS 16
#define C_OUT 64
#define HD (H * DS)  // 4096

// ---------------------------------------------------------------------------
// Scratch (device globals; no allocation allowed)
// ---------------------------------------------------------------------------
__device__ __align__(128) float g_x0[(size_t)T * V * C_IN];
__device__ __align__(128) float g_x1[(size_t)T * V * H];
__device__ __align__(128) float g_h [(size_t)T * V * H];
__device__ __align__(128) float g_xsr[(size_t)T * V * H];
__device__ __align__(128) float g_agg[(size_t)T * V * H];
__device__ __align__(128) float g_deg[(size_t)T * V];
__device__ __align__(128) float g_state[(size_t)V * HD];
__device__ __align__(128) float g_lam[2 * HD];
__device__ __align__(128) float g_xlast[(size_t)V * H];
__device__ __align__(128) float g_xsrl [(size_t)V * H];
__device__ int g_is64;

// bf16 hi/lo split A operands
__device__ __align__(128) __nv_bfloat16 g_Acat_h[(size_t)T * V * 512];
__device__ __align__(128) __nv_bfloat16 g_Acat_l[(size_t)T * V * 512];
__device__ __align__(128) __nv_bfloat16 g_Amix_h[(size_t)V * HD];
__device__ __align__(128) __nv_bfloat16 g_Amix_l[(size_t)V * HD];

// bf16 hi/lo split, transposed weights ([N=256][K], K-major)
__device__ __align__(128) __nv_bfloat16 g_cat0_h[256 * 256], g_cat0_l[256 * 256];
__device__ __align__(128) __nv_bfloat16 g_cat1_h[256 * 512], g_cat1_l[256 * 512];
__device__ __align__(128) __nv_bfloat16 g_res0_h[256 * 128], g_res0_l[256 * 128];
__device__ __align__(128) __nv_bfloat16 g_mix0_h[256 * HD],  g_mix0_l[256 * HD];
__device__ __align__(128) __nv_bfloat16 g_mix1_h[256 * HD],  g_mix1_l[256 * HD];

// ---------------------------------------------------------------------------
// Helpers
// ---------------------------------------------------------------------------
__device__ __forceinline__ uint32_t smem_u32(const void* p) {
    uint32_t a;
    asm("{ .reg .u64 t; cvta.to.shared.u64 t, %1; cvt.u32.u64 %0, t; }" : "=r"(a) : "l"(p));
    return a;
}

__device__ __forceinline__ void bf_split(float x, __nv_bfloat16& h_, __nv_bfloat16& l_) {
    h_ = __float2bfloat16(x);
    l_ = __float2bfloat16(x - __bfloat162float(h_));
}

#define LDSM_X4(r0, r1, r2, r3, addr) \
    asm volatile("ldmatrix.sync.aligned.m8n8.x4.shared.b16 {%0,%1,%2,%3}, [%4];" \
        : "=r"(r0), "=r"(r1), "=r"(r2), "=r"(r3) : "r"(addr))

#define MMA_BF16(d, a, b0, b1) \
    asm volatile("mma.sync.aligned.m16n8k16.row.col.f32.bf16.bf16.f32 " \
        "{%0,%1,%2,%3}, {%4,%5,%6,%7}, {%8,%9}, {%0,%1,%2,%3};" \
        : "+f"((d)[0]), "+f"((d)[1]), "+f"((d)[2]), "+f"((d)[3]) \
        : "r"((a)[0]), "r"((a)[1]), "r"((a)[2]), "r"((a)[3]), "r"(b0), "r"(b1))

// ---------------------------------------------------------------------------
// Small kernels
// ---------------------------------------------------------------------------
__global__ void zero_kernel(float4* p, long long n4) {
    long long i = blockIdx.x * (long long)blockDim.x + threadIdx.x;
    long long stride = (long long)gridDim.x * blockDim.x;
    for (; i < n4; i += stride) p[i] = make_float4(0.f, 0.f, 0.f, 0.f);
}

__global__ void detect_kernel(const unsigned int* ei) {
    if (threadIdx.x == 0 && blockIdx.x == 0) {
        unsigned int s = 0;
        for (int i = 0; i < 64; i++) s |= ei[2 * i + 1];
        g_is64 = (s == 0) ? 1 : 0;
    }
}

__device__ __forceinline__ int load_edge(const void* ei, long long pos) {
    if (g_is64) return (int)((const long long*)ei)[pos];
    return ((const int*)ei)[pos];
}

__global__ void lam_kernel(const float* a0, const float* a1, float* lam) {
    int i = blockIdx.x * blockDim.x + threadIdx.x;
    if (i < HD)           lam[i] = expf(-expf(a0[i]));
    else if (i < 2 * HD)  lam[i] = expf(-expf(a1[i - HD]));
}

__global__ void token_mix_kernel(const float* __restrict__ xs,
                                 const float* __restrict__ w,
                                 const float* __restrict__ b,
                                 float* __restrict__ out) {
    int idx = blockIdx.x * blockDim.x + threadIdx.x;
    if (idx >= T * V * C_IN) return;
    int c = idx % C_IN;
    int t = idx / (V * C_IN);
    float acc = b[c] + xs[idx] * w[c * 3 + 1];
    if (t > 0)     acc += xs[idx - V * C_IN] * w[c * 3 + 0];
    if (t < T - 1) acc += xs[idx + V * C_IN] * w[c * 3 + 2];
    out[idx] = acc;
}

__global__ void deg_kernel(const void* __restrict__ ei, float* __restrict__ deg) {
    long long i = blockIdx.x * (long long)blockDim.x + threadIdx.x;
    if (i >= (long long)T * E) return;
    int e = (int)(i % E);
    int t = (int)(i / E);
    int dst = load_edge(ei, (long long)t * 2 * E + E + e);
    atomicAdd(&deg[(long long)t * V + dst], 1.0f);
}

__global__ void scatter_kernel(const float* __restrict__ x, const void* __restrict__ ei,
                               float* __restrict__ agg, int C) {
    int chunks = C >> 2;
    long long idx = blockIdx.x * (long long)blockDim.x + threadIdx.x;
    long long total = (long long)T * E * chunks;
    if (idx >= total) return;
    int c4 = (int)(idx % chunks);
    long long te = idx / chunks;
    int e = (int)(te % E);
    int t = (int)(te / E);
    long long base = (long long)t * 2 * E;
    int src = load_edge(ei, base + e);
    int dst = load_edge(ei, base + E + e);
    float4 v = *(const float4*)&x[((long long)t * V + src) * C + c4 * 4];
    float* p = &agg[((long long)t * V + dst) * C + c4 * 4];
    asm volatile("red.global.add.v4.f32 [%0], {%1,%2,%3,%4};"
                 :: "l"(p), "f"(v.x), "f"(v.y), "f"(v.z), "f"(v.w) : "memory");
}

__global__ void mean_kernel(float* __restrict__ agg, const float* __restrict__ deg, int C) {
    int chunks = C >> 2;
    long long idx = blockIdx.x * (long long)blockDim.x + threadIdx.x;
    long long total = (long long)T * V * chunks;
    if (idx >= total) return;
    long long row = idx / chunks;
    int c4 = (int)(idx % chunks);
    float inv = 1.0f / fmaxf(deg[row], 1.0f);
    float4* p = (float4*)&agg[row * C + c4 * 4];
    float4 v = *p;
    v.x *= inv; v.y *= inv; v.z *= inv; v.w *= inv;
    *p = v;
}

// Roll SSM state forward over steps [0, nsteps) from zero state (fp32).
__global__ void ssm_collapse_kernel(const float* __restrict__ h,
                                    float* __restrict__ state,
                                    const float* __restrict__ lam,
                                    const float* __restrict__ Bp, int nsteps) {
    long long idx = blockIdx.x * (long long)blockDim.x + threadIdx.x;
    if (idx >= (long long)V * HD / 4) return;
    long long base = idx * 4;
    int hd = (int)(base % HD);
    int v  = (int)(base / HD);
    int hh = hd / DS;
    float4 l = *(const float4*)&lam[hd];
    float4 b = *(const float4*)&Bp[hd];
    float4 s = make_float4(0.f, 0.f, 0.f, 0.f);
    for (int t = 0; t < nsteps; t++) {
        float x = h[((long long)t * V + v) * H + hh];
        s.x = l.x * s.x + x * b.x;
        s.y = l.y * s.y + x * b.y;
        s.z = l.z * s.z + x * b.z;
        s.w = l.w * s.w + x * b.w;
    }
    *(float4*)&state[base] = s;
}

// Build transposed, bf16-split weights: dst[n][k] (K-major) from w1/w2 [K][256]
__global__ void bsplit_kernel(const float* __restrict__ w1, const float* __restrict__ w2,
                              int K1, int Kt,
                              __nv_bfloat16* __restrict__ hi, __nv_bfloat16* __restrict__ lo) {
    long long idx = blockIdx.x * (long long)blockDim.x + threadIdx.x;
    if (idx >= (long long)Kt * 256) return;
    int k = (int)(idx % Kt);
    int n = (int)(idx / Kt);
    float v = (k < K1) ? w1[(long long)k * 256 + n] : w2[(long long)(k - K1) * 256 + n];
    __nv_bfloat16 h_, l_;
    bf_split(v, h_, l_);
    hi[(long long)n * Kt + k] = h_;
    lo[(long long)n * Kt + k] = l_;
}

// A-operand split: concat(A1[M,K1], A2[M,K2]) -> bf16 hi/lo [M, K1+K2]
__global__ void asplit_concat_kernel(const float* __restrict__ A1, const float* __restrict__ A2,
                                     int K1, int K2, long long M,
                                     __nv_bfloat16* __restrict__ Ah, __nv_bfloat16* __restrict__ Al) {
    int Kt = K1 + K2;
    long long idx = blockIdx.x * (long long)blockDim.x + threadIdx.x;
    long long tot = M * (Kt / 4);
    if (idx >= tot) return;
    long long row = idx / (Kt / 4);
    int kq = (int)(idx % (Kt / 4)) * 4;
    float4 v = (kq < K1) ? *(const float4*)&A1[row * K1 + kq]
                         : *(const float4*)&A2[row * K2 + (kq - K1)];
    __nv_bfloat16 h0, l0, h1, l1, h2, l2, h3, l3;
    bf_split(v.x, h0, l0); bf_split(v.y, h1, l1);
    bf_split(v.z, h2, l2); bf_split(v.w, h3, l3);
    __nv_bfloat162* ph = (__nv_bfloat162*)&Ah[row * Kt + kq];
    __nv_bfloat162* pl = (__nv_bfloat162*)&Al[row * Kt + kq];
    ph[0] = __nv_bfloat162{h0, h1}; ph[1] = __nv_bfloat162{h2, h3};
    pl[0] = __nv_bfloat162{l0, l1}; pl[1] = __nv_bfloat162{l2, l3};
}

// Fused SSM update + relu + bf16 split:  state = lam*state + h_t⊗B;  A = relu(state)
__global__ void asplit_update_kernel(const float* __restrict__ h_t,
                                     float* __restrict__ state,
                                     const float* __restrict__ lam,
                                     const float* __restrict__ Bp,
                                     __nv_bfloat16* __restrict__ Ah,
                                     __nv_bfloat16* __restrict__ Al, int init) {
    long long idx = blockIdx.x * (long long)blockDim.x + threadIdx.x;
    if (idx >= (long long)V * HD / 4) return;
    long long base = idx * 4;
    int hd = (int)(base % HD);
    int v  = (int)(base / HD);
    int hh = hd / DS;
    float4 s = init ? make_float4(0.f, 0.f, 0.f, 0.f) : *(float4*)&state[base];
    float4 l = *(const float4*)&lam[hd];
    float4 b = *(const float4*)&Bp[hd];
    float x = h_t[(long long)v * H + hh];
    s.x = l.x * s.x + x * b.x;
    s.y = l.y * s.y + x * b.y;
    s.z = l.z * s.z + x * b.z;
    s.w = l.w * s.w + x * b.w;
    *(float4*)&state[base] = s;
    __nv_bfloat16 h0, l0, h1, l1, h2, l2, h3, l3;
    bf_split(fmaxf(s.x, 0.f), h0, l0);
    bf_split(fmaxf(s.y, 0.f), h1, l1);
    bf_split(fmaxf(s.z, 0.f), h2, l2);
    bf_split(fmaxf(s.w, 0.f), h3, l3);
    __nv_bfloat162* ph = (__nv_bfloat162*)&Ah[base];
    __nv_bfloat162* pl = (__nv_bfloat162*)&Al[base];
    ph[0] = __nv_bfloat162{h0, h1}; ph[1] = __nv_bfloat162{h2, h3};
    pl[0] = __nv_bfloat162{l0, l1}; pl[1] = __nv_bfloat162{l2, l3};
}

// ---------------------------------------------------------------------------
// bf16x3 mma.sync GEMM:  C[M,256] = (Ah+Al)[M,K] @ (Bh+Bl)[K,256] + bias + D
// Tile 128x128, BK=32, 256 threads (8 warps, 2m x 4n, warp tile 64x32).
// Double-buffered smem, reg-staged global prefetch.
// ---------------------------------------------------------------------------
#define BK 32
#define ROWB 80                 // (32+8) bf16 * 2B, padded row
#define ATILE 10240             // 128 * 80
#define STG (4 * ATILE)         // As_h, As_l, Bs_h, Bs_l
#define GSMEM (2 * STG)

__global__ __launch_bounds__(256, 1) void tgemm_kernel(
    const __nv_bfloat16* __restrict__ Ah, const __nv_bfloat16* __restrict__ Al,
    const __nv_bfloat16* __restrict__ Bh, const __nv_bfloat16* __restrict__ Bl,
    const float* __restrict__ bias, const float* __restrict__ Dadd,
    float* __restrict__ Cout, int M, int Kused, int Kstride)
{
    extern __shared__ char smem[];
    const uint32_t sb = smem_u32(smem);
    const int tid = threadIdx.x;
    const int wid = tid >> 5;
    const int lane = tid & 31;
    const int warp_m = wid >> 2;       // 0..1
    const int warp_n = wid & 3;        // 0..3
    const long long m0 = (long long)blockIdx.x * 128;
    const int n0 = blockIdx.y * 128;

    // per-thread load coords (2 chunks of 8 bf16 per operand)
    const int c0 = tid * 2;
    const int row0 = c0 >> 2;          // 0..127
    const int kq0 = (c0 & 3) * 8;      // 0,8,16,24 ; second chunk = +8

    float acc[4][4][4];
#pragma unroll
    for (int i = 0; i < 4; i++)
#pragma unroll
        for (int j = 0; j < 4; j++)
#pragma unroll
            for (int q = 0; q < 4; q++) acc[i][j][q] = 0.f;

    const int nK = Kused / BK;
    uint4 pa[4], pb[4];
    const uint4 zz = make_uint4(0, 0, 0, 0);

    // ldmatrix base offsets (bytes within a stage)
    const uint32_t a_off = (uint32_t)(warp_m * 64 + (lane & 15)) * ROWB +
                           (uint32_t)((lane >> 4) << 3) * 2;
    const uint32_t b_off = (uint32_t)(warp_n * 32 + ((lane >> 4) << 3) + (lane & 7)) * ROWB +
                           (uint32_t)(((lane >> 3) & 1) << 3) * 2;

    auto gload = [&](int kt) {
        const int k0 = kt * BK;
#pragma unroll
        for (int i = 0; i < 2; i++) {
            int row = row0 + (i & 1) * 0;  // same row, chunks differ in kq
            int kq = kq0 + i * 8;
            long long rg = m0 + row;
            long long aoff = rg * Kstride + k0 + kq;
            bool ok = (rg < M);
            pa[i]     = ok ? *(const uint4*)&Ah[aoff] : zz;
            pa[2 + i] = ok ? *(const uint4*)&Al[aoff] : zz;
            long long boff = (long long)(n0 + row) * Kused + k0 + kq;
            pb[i]     = *(const uint4*)&Bh[boff];
            pb[2 + i] = *(const uint4*)&Bl[boff];
        }
    };
    auto sstore = [&](int stage) {
        const uint32_t base = sb + stage * STG;
#pragma unroll
        for (int i = 0; i < 2; i++) {
            int kq = kq0 + i * 8;
            uint32_t off = (uint32_t)row0 * ROWB + kq * 2;
            *(uint4*)(smem + (base - sb) + off)              = pa[i];
            *(uint4*)(smem + (base - sb) + ATILE + off)      = pa[2 + i];
            *(uint4*)(smem + (base - sb) + 2 * ATILE + off)  = pb[i];
            *(uint4*)(smem + (base - sb) + 3 * ATILE + off)  = pb[2 + i];
        }
    };
    auto compute = [&](int stage) {
        const uint32_t base = sb + stage * STG;
#pragma unroll
        for (int ks = 0; ks < 2; ks++) {
            const uint32_t kk2 = (uint32_t)(ks * 16) * 2;   // byte offset of k-step
            uint32_t a_h[4][4], a_l[4][4];
#pragma unroll
            for (int i = 0; i < 4; i++) {
                uint32_t ad = base + a_off + (uint32_t)(i * 16) * ROWB + kk2;
                LDSM_X4(a_h[i][0], a_h[i][1], a_h[i][2], a_h[i][3], ad);
                LDSM_X4(a_l[i][0], a_l[i][1], a_l[i][2], a_l[i][3], ad + ATILE);
            }
            uint32_t b_h[8], b_l[8];
#pragma unroll
            for (int jj = 0; jj < 2; jj++) {
                uint32_t bd = base + 2 * ATILE + b_off + (uint32_t)(jj * 16) * ROWB + kk2;
                LDSM_X4(b_h[jj * 4 + 0], b_h[jj * 4 + 1], b_h[jj * 4 + 2], b_h[jj * 4 + 3], bd);
                LDSM_X4(b_l[jj * 4 + 0], b_l[jj * 4 + 1], b_l[jj * 4 + 2], b_l[jj * 4 + 3], bd + ATILE);
            }
#pragma unroll
            for (int i = 0; i < 4; i++)
#pragma unroll
                for (int j = 0; j < 4; j++) {
                    MMA_BF16(acc[i][j], a_h[i], b_h[j * 2], b_h[j * 2 + 1]);
                    MMA_BF16(acc[i][j], a_h[i], b_l[j * 2], b_l[j * 2 + 1]);
                    MMA_BF16(acc[i][j], a_l[i], b_h[j * 2], b_h[j * 2 + 1]);
                }
        }
    };

    gload(0);
    sstore(0);
    __syncthreads();
    for (int kt = 0; kt < nK; kt++) {
        int cur = kt & 1;
        if (kt + 1 < nK) gload(kt + 1);
        compute(cur);
        if (kt + 1 < nK) sstore(cur ^ 1);
        __syncthreads();
    }

    // epilogue
#pragma unroll
    for (int i = 0; i < 4; i++) {
        long long r1 = m0 + warp_m * 64 + i * 16 + (lane >> 2);
        long long r2 = r1 + 8;
#pragma unroll
        for (int j = 0; j < 4; j++) {
            int c = n0 + warp_n * 32 + j * 8 + (lane & 3) * 2;
            float bx = 0.f, by = 0.f;
            if (bias) { float2 b2 = *(const float2*)&bias[c]; bx = b2.x; by = b2.y; }
            if (r1 < M) {
                float2 v = make_float2(acc[i][j][0] + bx, acc[i][j][1] + by);
                if (Dadd) { float2 d = *(const float2*)&Dadd[r1 * 256 + c]; v.x += d.x; v.y += d.y; }
                *(float2*)&Cout[r1 * 256 + c] = v;
            }
            if (r2 < M) {
                float2 v = make_float2(acc[i][j][2] + bx, acc[i][j][3] + by);
                if (Dadd) { float2 d = *(const float2*)&Dadd[r2 * 256 + c]; v.x += d.x; v.y += d.y; }
                *(float2*)&Cout[r2 * 256 + c] = v;
            }
        }
    }
}

// ---------------------------------------------------------------------------
// fp32 SGEMM for the small output head (N=64)
// ---------------------------------------------------------------------------
#define BMH 128
#define BNH 128
#define BKH 8

__global__ __launch_bounds__(256) void sgemm_kernel(
    const float* __restrict__ A, const float* __restrict__ B,
    const float* __restrict__ bias, float* __restrict__ C, int M, int N, int K)
{
    __shared__ float As[BKH][BMH];
    __shared__ float Bs[BKH][BNH];
    int row0 = blockIdx.y * BMH;
    int col0 = blockIdx.x * BNH;
    int tid = threadIdx.x;
    int aRow = tid >> 1;
    int aCol = (tid & 1) * 4;
    int bRow = tid >> 5;
    int bCol = (tid & 31) * 4;
    int tx = tid & 15;
    int ty = tid >> 4;
    float acc[8][8];
#pragma unroll
    for (int i = 0; i < 8; i++)
#pragma unroll
        for (int j = 0; j < 8; j++) acc[i][j] = 0.f;
    int nK = K / BKH;
    for (int kt = 0; kt < nK; ++kt) {
        int k0 = kt * BKH;
        float4 av = make_float4(0.f, 0.f, 0.f, 0.f);
        int gr = row0 + aRow;
        if (gr < M) av = *(const float4*)&A[(long long)gr * K + k0 + aCol];
        As[aCol + 0][aRow] = av.x;
        As[aCol + 1][aRow] = av.y;
        As[aCol + 2][aRow] = av.z;
        As[aCol + 3][aRow] = av.w;
        float4 bv = make_float4(0.f, 0.f, 0.f, 0.f);
        int gc = col0 + bCol;
        if (gc < N) bv = *(const float4*)&B[(long long)(k0 + bRow) * N + gc];
        *(float4*)&Bs[bRow][bCol] = bv;
        __syncthreads();
#pragma unroll
        for (int k = 0; k < BKH; k++) {
            float ar[8], br[8];
#pragma unroll
            for (int i = 0; i < 8; i++) ar[i] = As[k][ty * 8 + i];
#pragma unroll
            for (int j = 0; j < 8; j++) br[j] = Bs[k][tx * 8 + j];
#pragma unroll
            for (int i = 0; i < 8; i++)
#pragma unroll
                for (int j = 0; j < 8; j++) acc[i][j] += ar[i] * br[j];
        }
        __syncthreads();
    }
#pragma unroll
    for (int i = 0; i < 8; i++) {
        int r = row0 + ty * 8 + i;
        if (r >= M) continue;
#pragma unroll
        for (int j = 0; j < 8; j++) {
            int c = col0 + tx * 8 + j;
            if (c >= N) continue;
            C[(long long)r * N + c] = acc[i][j] + bias[c];
        }
    }
}

// ---------------------------------------------------------------------------
// Host helpers
// ---------------------------------------------------------------------------
static void zero_buf(float* p, long long n_floats) {
    zero_kernel<<<1024, 256>>>((float4*)p, n_floats / 4);
}

static void tgemm(const __nv_bfloat16* Ah, const __nv_bfloat16* Al,
                  const __nv_bfloat16* Bh, const __nv_bfloat16* Bl,
                  const float* bias, const float* Dadd, float* C,
                  long long M, int Kused, int Kstride) {
    dim3 grid((unsigned)((M + 127) / 128), 2);
    tgemm_kernel<<<grid, 256, GSMEM>>>(Ah, Al, Bh, Bl, bias, Dadd, C,
                                       (int)M, Kused, Kstride);
}

// ---------------------------------------------------------------------------
// Launch
// ---------------------------------------------------------------------------
extern "C" void kernel_launch(void* const* d_in, const int* in_sizes, int n_in,
                              void* d_out, int out_size) {
    const float* xs      = (const float*)d_in[0];
    const void*  ei      = d_in[1];
    const float* w_pre   = (const float*)d_in[2];
    const float* b_pre   = (const float*)d_in[3];

    const float* w_res0  = (const float*)d_in[4];
    const float* b_res0  = (const float*)d_in[5];
    const float* w_self0 = (const float*)d_in[6];
    const float* w_neigh0= (const float*)d_in[7];
    const float* b_sage0 = (const float*)d_in[8];
    const float* a_log0  = (const float*)d_in[9];
    const float* B0      = (const float*)d_in[10];
    const float* w_mix0  = (const float*)d_in[11];
    const float* b_mix0  = (const float*)d_in[12];

    const float* w_res1  = (const float*)d_in[13];
    const float* b_res1  = (const float*)d_in[14];
    const float* w_self1 = (const float*)d_in[15];
    const float* w_neigh1= (const float*)d_in[16];
    const float* b_sage1 = (const float*)d_in[17];
    const float* a_log1  = (const float*)d_in[18];
    const float* B1      = (const float*)d_in[19];
    const float* w_mix1  = (const float*)d_in[20];
    const float* b_mix1  = (const float*)d_in[21];

    const float* w_out   = (const float*)d_in[22];
    const float* b_out   = (const float*)d_in[23];

    float *x0, *x1, *h, *xsr, *agg, *deg, *state, *lam, *xlast, *xsrl;
    cudaGetSymbolAddress((void**)&x0,    g_x0);
    cudaGetSymbolAddress((void**)&x1,    g_x1);
    cudaGetSymbolAddress((void**)&h,     g_h);
    cudaGetSymbolAddress((void**)&xsr,   g_xsr);
    cudaGetSymbolAddress((void**)&agg,   g_agg);
    cudaGetSymbolAddress((void**)&deg,   g_deg);
    cudaGetSymbolAddress((void**)&state, g_state);
    cudaGetSymbolAddress((void**)&lam,   g_lam);
    cudaGetSymbolAddress((void**)&xlast, g_xlast);
    cudaGetSymbolAddress((void**)&xsrl,  g_xsrl);

    __nv_bfloat16 *Acat_h, *Acat_l, *Amix_h, *Amix_l;
    __nv_bfloat16 *cat0h, *cat0l, *cat1h, *cat1l, *res0h, *res0l;
    __nv_bfloat16 *mix0h, *mix0l, *mix1h, *mix1l;
    cudaGetSymbolAddress((void**)&Acat_h, g_Acat_h);
    cudaGetSymbolAddress((void**)&Acat_l, g_Acat_l);
    cudaGetSymbolAddress((void**)&Amix_h, g_Amix_h);
    cudaGetSymbolAddress((void**)&Amix_l, g_Amix_l);
    cudaGetSymbolAddress((void**)&cat0h, g_cat0_h);
    cudaGetSymbolAddress((void**)&cat0l, g_cat0_l);
    cudaGetSymbolAddress((void**)&cat1h, g_cat1_h);
    cudaGetSymbolAddress((void**)&cat1l, g_cat1_l);
    cudaGetSymbolAddress((void**)&res0h, g_res0_h);
    cudaGetSymbolAddress((void**)&res0l, g_res0_l);
    cudaGetSymbolAddress((void**)&mix0h, g_mix0_h);
    cudaGetSymbolAddress((void**)&mix0l, g_mix0_l);
    cudaGetSymbolAddress((void**)&mix1h, g_mix1_h);
    cudaGetSymbolAddress((void**)&mix1l, g_mix1_l);

    cudaFuncSetAttribute(tgemm_kernel,
                         cudaFuncAttributeMaxDynamicSharedMemorySize, GSMEM);

    detect_kernel<<<1, 32>>>((const unsigned int*)ei);
    lam_kernel<<<(2 * HD + 255) / 256, 256>>>(a_log0, a_log1, lam);
    token_mix_kernel<<<(T * V * C_IN + 255) / 256, 256>>>(xs, w_pre, b_pre, x0);

    // weight preprocessing
    {
        auto bs = [](const float* w1, const float* w2, int K1, int Kt,
                     __nv_bfloat16* hi, __nv_bfloat16* lo) {
            long long tot = (long long)Kt * 256;
            bsplit_kernel<<<(int)((tot + 255) / 256), 256>>>(w1, w2, K1, Kt, hi, lo);
        };
        bs(w_self0, w_neigh0, C_IN, 2 * C_IN, cat0h, cat0l);
        bs(w_self1, w_neigh1, H, 2 * H, cat1h, cat1l);
        bs(w_res0, nullptr, C_IN, C_IN, res0h, res0l);
        bs(w_mix0, nullptr, HD, HD, mix0h, mix0l);
        bs(w_mix1, nullptr, HD, HD, mix1h, mix1l);
    }

    // degrees (shared by both layers)
    zero_buf(deg, (long long)T * V);
    deg_kernel<<<(int)(((long long)T * E + 255) / 256), 256>>>(ei, deg);

    const long long TV = (long long)T * V;
    const long long VHD4 = (long long)V * HD / 4;

    // ---------------- layer 0 ----------------
    zero_buf(agg, TV * C_IN);
    {
        long long tot = TV * E / V * (C_IN / 4);    // T*E*(C_IN/4)
        scatter_kernel<<<(int)((tot + 255) / 256), 256>>>(x0, ei, agg, C_IN);
        long long tm = TV * (C_IN / 4);
        mean_kernel<<<(int)((tm + 255) / 256), 256>>>(agg, deg, C_IN);
    }
    {
        long long tot = TV * (2 * C_IN) / 4;
        asplit_concat_kernel<<<(int)((tot + 255) / 256), 256>>>(
            x0, agg, C_IN, C_IN, TV, Acat_h, Acat_l);
    }
    tgemm(Acat_h, Acat_l, cat0h, cat0l, b_sage0, nullptr, h,   TV, 2 * C_IN, 2 * C_IN);
    // res0: reuse first K=128 columns of the concat split
    tgemm(Acat_h, Acat_l, res0h, res0l, b_res0, nullptr, xsr,  TV, C_IN, 2 * C_IN);

    for (int t = 0; t < T; t++) {
        asplit_update_kernel<<<(int)((VHD4 + 255) / 256), 256>>>(
            h + (long long)t * V * H, state, lam, B0, Amix_h, Amix_l, t == 0);
        tgemm(Amix_h, Amix_l, mix0h, mix0l, b_mix0, xsr + (long long)t * V * H,
              x1 + (long long)t * V * H, V, HD, HD);
    }

    // ---------------- layer 1 ----------------
    zero_buf(agg, TV * H);
    {
        long long tot = (long long)T * E * (H / 4);
        scatter_kernel<<<(int)((tot + 255) / 256), 256>>>(x1, ei, agg, H);
        long long tm = TV * (H / 4);
        mean_kernel<<<(int)((tm + 255) / 256), 256>>>(agg, deg, H);
    }
    {
        long long tot = TV * (2 * H) / 4;
        asplit_concat_kernel<<<(int)((tot + 255) / 256), 256>>>(
            x1, agg, H, H, TV, Acat_h, Acat_l);
    }
    tgemm(Acat_h, Acat_l, cat1h, cat1l, b_sage1, nullptr, h, TV, 2 * H, 2 * H);
    // res1 at t=T-1 only: first 256 cols of concat rows [7V, 8V)
    {
        long long off = (long long)(T - 1) * V * (2 * H);
        // reuse cat1's w_res1 split: build it on the fly into res0 buffers? No —
        // w_res1 is 256x256; split it into cat0 buffers (256*256) which are free now.
        bsplit_kernel<<<(int)(((long long)256 * 256 + 255) / 256), 256>>>(
            w_res1, nullptr, H, H, cat0h, cat0l);
        tgemm(Acat_h + off, Acat_l + off, cat0h, cat0l, b_res1, nullptr, xsrl,
              V, H, 2 * H);
    }

    // roll state forward through t=0..6 (no GEMMs needed)
    ssm_collapse_kernel<<<(int)((VHD4 + 255) / 256), 256>>>(h, state, lam + HD, B1, T - 1);
    // t=7: update + split + mix GEMM
    asplit_update_kernel<<<(int)((VHD4 + 255) / 256), 256>>>(
        h + (long long)(T - 1) * V * H, state, lam + HD, B1, Amix_h, Amix_l, 0);
    tgemm(Amix_h, Amix_l, mix1h, mix1l, b_mix1, xsrl, xlast, V, HD, HD);

    // ---------------- output head ----------------
    dim3 og((C_OUT + BNH - 1) / BNH, (V + BMH - 1) / BMH);
    sgemm_kernel<<<og, 256>>>(xlast, w_out, b_out, (float*)d_out, V, C_OUT, H);
}